// round 14
// baseline (speedup 1.0000x reference)
#include <cuda_runtime.h>
#include <cstdint>

// CTC prefix beam search — bit-exact vs JAX reference.
// R12-R14: TWO independent chains per warp (QQ=2), phase-interleaved so each
//      chain's REDUX/shfl/MUFU latency is hidden by the other chain's
//      independent instructions. Math identical to validated R10 (u64 keys).

#define BATCH 1024
#define TT    128
#define CCC   63
#define VVV   62
#define WW    8
#define NEGF  (-1e30f)
#define HB1C  1000003u
#define HB2C  2654435761u
#define WPB   4
#define QQ    2
#define FULL  0xffffffffu

typedef unsigned long long u64;
typedef unsigned int u32;

__device__ __forceinline__ float lax_logaddexp(float a, float b) {
    float m = fmaxf(a, b);
    return m + log1pf(expf(-fabsf(a - b)));
}
__device__ __forceinline__ float seg_lse2(float a, float b) {
    float m = fmaxf(a, b);
    float s = expf(a - m) + expf(b - m);
    return logf(fmaxf(s, 1e-30f)) + m;
}
__device__ __forceinline__ u32 ord_of_float(float f) {
    u32 u = __float_as_uint(f);
    return (u & 0x80000000u) ? ~u : (u | 0x80000000u);
}
__device__ __forceinline__ float float_of_ord(u32 u) {
    return __uint_as_float((u & 0x80000000u) ? (u & 0x7fffffffu) : ~u);
}
__device__ __forceinline__ u64 kmax(u64 a, u64 b) { return a > b ? a : b; }
__device__ __forceinline__ void cex(u64& a, u64& b) {
    u64 mx = a > b ? a : b;
    u64 mn = a > b ? b : a;
    a = mx; b = mn;
}
// bitonic merge (desc) of a bitonic 8-seq -> sorted desc (validated R8/R10)
#define BMERGE8(T)                                                   \
    do {                                                             \
        cex(T[0], T[4]); cex(T[1], T[5]); cex(T[2], T[6]); cex(T[3], T[7]); \
        cex(T[0], T[2]); cex(T[1], T[3]); cex(T[4], T[6]); cex(T[5], T[7]); \
        cex(T[0], T[1]); cex(T[2], T[3]); cex(T[4], T[5]); cex(T[6], T[7]); \
    } while (0)
// Batcher 19-CE sort (desc) of 8 (validated R8/R10)
#define SORT8(K, O)                                                     \
    do {                                                                \
        cex(K[O+0],K[O+1]); cex(K[O+2],K[O+3]); cex(K[O+4],K[O+5]); cex(K[O+6],K[O+7]); \
        cex(K[O+0],K[O+2]); cex(K[O+1],K[O+3]); cex(K[O+4],K[O+6]); cex(K[O+5],K[O+7]); \
        cex(K[O+1],K[O+2]); cex(K[O+5],K[O+6]);                          \
        cex(K[O+0],K[O+4]); cex(K[O+1],K[O+5]); cex(K[O+2],K[O+6]); cex(K[O+3],K[O+7]); \
        cex(K[O+2],K[O+4]); cex(K[O+3],K[O+5]);                          \
        cex(K[O+1],K[O+2]); cex(K[O+3],K[O+4]); cex(K[O+5],K[O+6]);      \
    } while (0)

__global__ void __launch_bounds__(32 * WPB, 1)
ctc_beam_kernel(const float* __restrict__ logits, float* __restrict__ out) {
    __shared__ unsigned short hist[WPB][QQ][TT * WW];  // (parent<<8)|(char+1)
    const int wip  = threadIdx.x >> 5;
    const int lane = threadIdx.x & 31;
    const int b0   = (blockIdx.x * WPB + wip) * QQ;
    const float NINF = __int_as_float(0xff800000);
    const u32 Mlow = ((u32)lane << 5) - ((u32)lane << 10);
    const u32 ordDeadThr = ord_of_float(0.5f * NEGF);

    const float* base[QQ];
    u32 bm_h1[QQ], bm_h2[QQ];
    float bm_pb[QQ], bm_pnb[QQ], bm_spb[QQ], bm_mpnb[QQ];
    int bm_last[QQ], bm_len[QQ];
    float lp0[QQ], lp1[QQ], nx0[QQ], nx1[QQ];

    #pragma unroll
    for (int q = 0; q < QQ; ++q) {
        base[q] = logits + (size_t)(b0 + q) * TT * CCC;
        bm_h1[q] = 1u; bm_h2[q] = 1u;
        bm_pb[q]  = (lane == 0) ? 0.0f : NEGF;
        bm_pnb[q] = NEGF;
        bm_last[q] = -1; bm_len[q] = 0;
        bm_spb[q] = NEGF; bm_mpnb[q] = NEGF;
        // softmax frame 0
        float cx0 = base[q][lane];
        float cx1 = (lane < 31) ? base[q][lane + 32] : NINF;
        u32 mo = __reduce_max_sync(FULL, ord_of_float(fmaxf(cx0, cx1)));
        float mx = float_of_ord(mo);
        float e0 = expf(cx0 - mx);
        float e1 = (lane < 31) ? expf(cx1 - mx) : 0.0f;
        float sm = e0 + e1;
        #pragma unroll
        for (int off = 16; off; off >>= 1)
            sm += __shfl_xor_sync(FULL, sm, off);
        float lse = logf(sm);
        lp0[q] = cx0 - mx - lse;
        lp1[q] = cx1 - mx - lse;
        // prefetch frame 1
        nx0[q] = base[q][CCC + lane];
        nx1[q] = (lane < 31) ? base[q][CCC + lane + 32] : NINF;
    }

    // duplicates exist ONLY at t=0 (validated R10, rel_err 0.0)
    u32 dupmask = 0xFEu;

    for (int t = 0; t < TT; ++t) {
        int dup = (int)((dupmask >> lane) & 1u);

        float bm_ptot[QQ], bm_spnb[QQ];
        int msrc[QQ];
        u32 killLo[QQ], killHi[QQ];

        // ---- 2a: per-beam prep (interleaved across chains) ----
        #pragma unroll
        for (int q = 0; q < QQ; ++q) {
            float lpBlank = __shfl_sync(FULL, lp1[q], 30);   // class 62
            int ls = (bm_last[q] >= 0) ? (bm_last[q] & 31) : 0;
            float v0 = __shfl_sync(FULL, lp0[q], ls);
            float v1 = __shfl_sync(FULL, lp1[q], ls);
            float lpLast = (bm_last[q] >= 32) ? v1 : v0;
            bm_ptot[q] = lax_logaddexp(bm_pb[q], bm_pnb[q]);
            bm_spb[q] = bm_ptot[q] + lpBlank;
            bm_spnb[q] = (bm_last[q] >= 0) ? (bm_pnb[q] + lpLast) : NEGF;
        }

        // ---- 2b: inverted merge detection + kill masks ----
        #pragma unroll
        for (int q = 0; q < QQ; ++q) {
            int ms = -1;
            #pragma unroll
            for (int i = 0; i < WW; ++i) {
                u32 ih1 = __shfl_sync(FULL, bm_h1[q], i);
                u32 ih2 = __shfl_sync(FULL, bm_h2[q], i);
                u32 c1 = bm_h1[q] - ih1 * HB1C - 1u;
                if (!((dupmask >> i) & 1u) && c1 < (u32)VVV &&
                    bm_h2[q] == ih2 * HB2C + c1 + 1u)
                    ms = i * 64 + (int)c1;
            }
            if (dup || lane >= WW) ms = -1;
            msrc[q] = ms;
        }
        #pragma unroll
        for (int q = 0; q < QQ; ++q) {
            u32 kl = dupmask, kh = dupmask;
            #pragma unroll
            for (int j = 0; j < WW; ++j) {
                int ms = __shfl_sync(FULL, msrc[q], j);
                if (ms >= 0) {
                    int mi = ms >> 6, mc = ms & 63;
                    if (mc == lane) kl |= 1u << mi;
                    if (mc == lane + 32) kh |= 1u << mi;
                }
            }
            killLo[q] = kl; killHi[q] = kh;
        }

        // ---- 3: extend keys + local sort (per-chain to cap reg pressure) ----
        u64 T[QQ][8];
        #pragma unroll
        for (int q = 0; q < QQ; ++q) {
            u64 key[16];
            #pragma unroll
            for (int i = 0; i < WW; ++i) {
                int   ilast = __shfl_sync(FULL, bm_last[q], i);
                float ipb   = __shfl_sync(FULL, bm_pb[q], i);
                float ipt   = __shfl_sync(FULL, bm_ptot[q], i);
                float sl = ((lane == ilast) ? ipb : ipt) + lp0[q];
                if ((killLo[q] >> i) & 1u) sl = NEGF;
                u32 lowl = (u32)(((u32)(1015 - 62 * i) << 10) + (u32)i) + Mlow;
                key[i] = ((u64)ord_of_float(sl) << 32) | lowl;
                float sh = ((lane + 32 == ilast) ? ipb : ipt) + lp1[q];
                if ((killHi[q] >> i) & 1u) sh = NEGF;
                u32 lowh = (u32)(((u32)(983 - 62 * i) << 10) + (u32)(i + 8)) + Mlow;
                u64 kh2 = ((u64)ord_of_float(sh) << 32) | lowh;
                key[i + 8] = (lane < 30) ? kh2 : 0ull;
            }
            SORT8(key, 0);
            SORT8(key, 8);
            u64 (&Tq)[8] = T[q];
            #pragma unroll
            for (int k = 0; k < 8; ++k) Tq[k] = kmax(key[k], key[15 - k]);
            BMERGE8(Tq);
        }

        // ---- merged stay pnb + stay key insert (MUFU chains interleaved) ----
        float cs0v[QQ];
        #pragma unroll
        for (int q = 0; q < QQ; ++q) {
            int mi = (msrc[q] >= 0) ? (msrc[q] >> 6) : 0;
            int mc = (msrc[q] >= 0) ? (msrc[q] & 63) : 0;
            float mpbv = __shfl_sync(FULL, bm_pb[q], mi);
            float mptv = __shfl_sync(FULL, bm_ptot[q], mi);
            int   mlv  = __shfl_sync(FULL, bm_last[q], mi);
            float w0 = __shfl_sync(FULL, lp0[q], mc & 31);
            float w1 = __shfl_sync(FULL, lp1[q], mc & 31);
            float lpc = (mc >= 32) ? w1 : w0;
            float bv = ((mc == mlv) ? mpbv : mptv) + lpc;
            bm_mpnb[q] = (msrc[q] >= 0) ? seg_lse2(bm_spnb[q], bv) : bm_spnb[q];
            cs0v[q] = dup ? NEGF : lax_logaddexp(bm_spb[q], bm_mpnb[q]);
        }
        #pragma unroll
        for (int q = 0; q < QQ; ++q) {
            u64 key16 = (lane < WW)
                ? (((u64)ord_of_float(cs0v[q]) << 32) |
                   (u32)(((1023u << 10) + 16u) + Mlow))
                : 0ull;
            u64 (&Tq)[8] = T[q];
            Tq[7] = kmax(Tq[7], key16);
            BMERGE8(Tq);          // local top-8 sorted desc
        }

        // ---- 3.5: OVERLAP — softmax of frame t+1 + prefetch t+2 ----
        float lpn0[QQ], lpn1[QQ];
        #pragma unroll
        for (int q = 0; q < QQ; ++q) {
            u32 mo = __reduce_max_sync(FULL, ord_of_float(fmaxf(nx0[q], nx1[q])));
            float mx = float_of_ord(mo);
            float e0 = expf(nx0[q] - mx);
            float e1 = (lane < 31) ? expf(nx1[q] - mx) : 0.0f;
            float sm = e0 + e1;
            #pragma unroll
            for (int off = 16; off; off >>= 1)
                sm += __shfl_xor_sync(FULL, sm, off);
            float lse = logf(sm);
            lpn0[q] = nx0[q] - mx - lse;
            lpn1[q] = nx1[q] - mx - lse;
        }
        {
            int tn = (t + 2 < TT) ? (t + 2) : (TT - 1);
            #pragma unroll
            for (int q = 0; q < QQ; ++q) {
                const float* nf = base[q] + tn * CCC;
                nx0[q] = nf[lane];
                nx1[q] = (lane < 31) ? nf[lane + 32] : NINF;
            }
        }

        // ---- 4: top-8 via REDUX head-pop, passes interleaved across chains ----
        u32 sel_m[QQ], sel_lo[QQ];
        #pragma unroll
        for (int q = 0; q < QQ; ++q) { sel_m[q] = 0u; sel_lo[q] = 0u; }
        #pragma unroll
        for (int k2 = 0; k2 < WW; ++k2) {
            #pragma unroll
            for (int q = 0; q < QQ; ++q) {
                u64 (&Tq)[8] = T[q];
                u32 hi = (u32)(Tq[0] >> 32), lo = (u32)Tq[0];
                u32 m  = __reduce_max_sync(FULL, hi);
                u32 tx = (hi == m) ? lo : 0u;
                u32 lw = __reduce_max_sync(FULL, tx);
                if (lane == k2) { sel_m[q] = m; sel_lo[q] = lw; }
                bool p = (lane == (int)((lw >> 5) & 31u));
                #pragma unroll
                for (int k = 0; k < 7; ++k) Tq[k] = p ? Tq[k + 1] : Tq[k];
                Tq[7] = p ? 0ull : Tq[7];
            }
        }

        // ---- 5: commit (gathers via shfl from OLD beam regs) ----
        #pragma unroll
        for (int q = 0; q < QQ; ++q) {
            int idx  = 1023 - (int)(sel_lo[q] >> 10);
            bool stay = idx < WW;
            int slot = (int)(sel_lo[q] & 31u);
            int wl   = (int)((sel_lo[q] >> 5) & 31u);
            int src  = stay ? idx : (slot & 7);
            int c    = wl + ((slot & 8) ? 32 : 0);
            u32 g_h1   = __shfl_sync(FULL, bm_h1[q], src);
            u32 g_h2   = __shfl_sync(FULL, bm_h2[q], src);
            int g_last = __shfl_sync(FULL, bm_last[q], src);
            int g_len  = __shfl_sync(FULL, bm_len[q], src);
            float g_spb  = __shfl_sync(FULL, bm_spb[q], src);
            float g_mpnb = __shfl_sync(FULL, bm_mpnb[q], src);
            if (lane < WW) {
                bool alive = sel_m[q] > ordDeadThr;
                float score = float_of_ord(sel_m[q]);
                float npb  = stay ? g_spb  : NEGF;
                float npnb = stay ? g_mpnb : score;
                if (!alive) { npb = NEGF; npnb = NEGF; }
                bm_pb[q] = npb; bm_pnb[q] = npnb;
                bm_h1[q] = stay ? g_h1 : (g_h1 * HB1C + (u32)(c + 1));
                bm_h2[q] = stay ? g_h2 : (g_h2 * HB2C + (u32)(c + 1));
                bm_last[q] = stay ? g_last : c;
                bm_len[q]  = g_len + (stay ? 0 : 1);
                hist[wip][q][t * WW + lane] = stay
                    ? (unsigned short)(idx << 8)
                    : (unsigned short)(((slot & 7) << 8) | (c + 1));
            }
            lp0[q] = lpn0[q]; lp1[q] = lpn1[q];
        }
        dupmask = 0u;          // duplicates only possible at t=0
    }

    // ---- outputs: decoded [B*128], lengths [B], prob [B], all f32 ----
    #pragma unroll
    for (int q = 0; q < QQ; ++q) {
        float* dec = out + (size_t)(b0 + q) * TT;
        #pragma unroll
        for (int s2 = 0; s2 < 4; ++s2)
            dec[lane + 32 * s2] = -1.0f;
    }
    __syncwarp();
    #pragma unroll
    for (int q = 0; q < QQ; ++q) {
        int len0 = __shfl_sync(FULL, bm_len[q], 0);
        float pb0  = __shfl_sync(FULL, bm_pb[q], 0);
        float pnb0 = __shfl_sync(FULL, bm_pnb[q], 0);
        if (lane == 0) {
            float* dec = out + (size_t)(b0 + q) * TT;
            int cur = 0;
            int pos = len0 - 1;
            for (int tt = TT - 1; tt >= 0; --tt) {
                unsigned short h = hist[wip][q][tt * WW + cur];
                int cc = (int)(h & 0xFF) - 1;
                cur = h >> 8;
                if (cc >= 0) dec[pos--] = (float)cc;
            }
            out[(size_t)BATCH * TT + (b0 + q)] = (float)len0;
            out[(size_t)BATCH * TT + BATCH + (b0 + q)] =
                expf(lax_logaddexp(pb0, pnb0));
        }
    }
}

extern "C" void kernel_launch(void* const* d_in, const int* in_sizes, int n_in,
                              void* d_out, int out_size) {
    const float* logits = (const float*)d_in[0];
    float* out = (float*)d_out;
    ctc_beam_kernel<<<BATCH / (WPB * QQ), 32 * WPB>>>(logits, out);
}

// round 15
// speedup vs baseline: 1.8199x; 1.8199x over previous
#include <cuda_runtime.h>
#include <cstdint>

// CTC prefix beam search — bit-exact vs JAX reference.
// One warp per batch element (1024 warps — TLP is load-bearing, R14 lesson).
// R15 = validated R10 + ALU-count cuts: ~bits ord encode (scores provably
// negative), 7-CE bubble insert for the stay key (replaces 12-CE merge).

#define BATCH 1024
#define TT    128
#define CCC   63
#define VVV   62
#define WW    8
#define NEGF  (-1e30f)
#define HB1C  1000003u
#define HB2C  2654435761u
#define WPB   4
#define FULL  0xffffffffu

typedef unsigned long long u64;
typedef unsigned int u32;

__device__ __forceinline__ float lax_logaddexp(float a, float b) {
    float m = fmaxf(a, b);
    return m + log1pf(expf(-fabsf(a - b)));
}
__device__ __forceinline__ float seg_lse2(float a, float b) {
    float m = fmaxf(a, b);
    float s = expf(a - m) + expf(b - m);
    return logf(fmaxf(s, 1e-30f)) + m;
}
__device__ __forceinline__ u32 ord_of_float(float f) {
    u32 u = __float_as_uint(f);
    return (u & 0x80000000u) ? ~u : (u | 0x80000000u);
}
// encode for STRICTLY NEGATIVE floats: identical to ord_of_float on negatives
__device__ __forceinline__ u32 ord_neg(float f) {
    return ~__float_as_uint(f);
}
__device__ __forceinline__ float float_of_ord(u32 u) {
    return __uint_as_float((u & 0x80000000u) ? (u & 0x7fffffffu) : ~u);
}
__device__ __forceinline__ u64 kmax(u64 a, u64 b) { return a > b ? a : b; }
__device__ __forceinline__ void cex(u64& a, u64& b) {
    u64 mx = a > b ? a : b;
    u64 mn = a > b ? b : a;
    a = mx; b = mn;
}
// bitonic merge (desc) of a bitonic 8-seq -> sorted desc (validated R8/R10)
#define BMERGE8(T)                                                   \
    do {                                                             \
        cex(T[0], T[4]); cex(T[1], T[5]); cex(T[2], T[6]); cex(T[3], T[7]); \
        cex(T[0], T[2]); cex(T[1], T[3]); cex(T[4], T[6]); cex(T[5], T[7]); \
        cex(T[0], T[1]); cex(T[2], T[3]); cex(T[4], T[5]); cex(T[6], T[7]); \
    } while (0)
// Batcher 19-CE sort (desc) of 8 (validated R8/R10)
#define SORT8(K, O)                                                     \
    do {                                                                \
        cex(K[O+0],K[O+1]); cex(K[O+2],K[O+3]); cex(K[O+4],K[O+5]); cex(K[O+6],K[O+7]); \
        cex(K[O+0],K[O+2]); cex(K[O+1],K[O+3]); cex(K[O+4],K[O+6]); cex(K[O+5],K[O+7]); \
        cex(K[O+1],K[O+2]); cex(K[O+5],K[O+6]);                          \
        cex(K[O+0],K[O+4]); cex(K[O+1],K[O+5]); cex(K[O+2],K[O+6]); cex(K[O+3],K[O+7]); \
        cex(K[O+2],K[O+4]); cex(K[O+3],K[O+5]);                          \
        cex(K[O+1],K[O+2]); cex(K[O+3],K[O+4]); cex(K[O+5],K[O+6]);      \
    } while (0)

__global__ void ctc_beam_kernel(const float* __restrict__ logits,
                                float* __restrict__ out) {
    __shared__ unsigned short hist[WPB][TT * WW];  // (parent<<8)|(char+1)
    const int wip  = threadIdx.x >> 5;
    const int lane = threadIdx.x & 31;
    const int b    = blockIdx.x * WPB + wip;
    const float* base = logits + (size_t)b * TT * CCC;
    const float NINF = __int_as_float(0xff800000);

    // beam state (valid on lanes 0..7; lane j == beam j)
    u32 bm_h1 = 1u, bm_h2 = 1u;
    float bm_pb  = (lane == 0) ? 0.0f : NEGF;
    float bm_pnb = NEGF;
    int bm_last = -1, bm_len = 0;
    float bm_spb = NEGF, bm_mpnb = NEGF;

    const u32 Mlow = ((u32)lane << 5) - ((u32)lane << 10);
    const u32 ordDeadThr = ord_of_float(0.5f * NEGF);

    // softmax frame 0
    float lp0, lp1;
    {
        float cx0 = base[lane];
        float cx1 = (lane < 31) ? base[lane + 32] : NINF;
        u32 mo = __reduce_max_sync(FULL, ord_of_float(fmaxf(cx0, cx1)));
        float mx = float_of_ord(mo);
        float e0 = expf(cx0 - mx);
        float e1 = (lane < 31) ? expf(cx1 - mx) : 0.0f;
        float sm = e0 + e1;
        #pragma unroll
        for (int off = 16; off; off >>= 1)
            sm += __shfl_xor_sync(FULL, sm, off);
        float lse = logf(sm);
        lp0 = cx0 - mx - lse;
        lp1 = cx1 - mx - lse;
    }
    // prefetch frame 1
    float nx0 = base[CCC + lane];
    float nx1 = (lane < 31) ? base[CCC + lane + 32] : NINF;

    // duplicates exist ONLY at t=0 (validated R10, rel_err 0.0)
    u32 dupmask = 0xFEu;

    for (int t = 0; t < TT; ++t) {
        int dup = (int)((dupmask >> lane) & 1u);

        // ---- 2a: per-beam prep ----
        float lpBlank = __shfl_sync(FULL, lp1, 30);   // class 62
        int ls = (bm_last >= 0) ? (bm_last & 31) : 0;
        float v0 = __shfl_sync(FULL, lp0, ls);
        float v1 = __shfl_sync(FULL, lp1, ls);
        float lpLast = (bm_last >= 32) ? v1 : v0;

        float bm_ptot = lax_logaddexp(bm_pb, bm_pnb);
        bm_spb = bm_ptot + lpBlank;
        float bm_spnb = (bm_last >= 0) ? (bm_pnb + lpLast) : NEGF;

        // ---- 2b: inverted merge detection ----
        int msrc = -1;
        #pragma unroll
        for (int i = 0; i < WW; ++i) {
            u32 ih1 = __shfl_sync(FULL, bm_h1, i);
            u32 ih2 = __shfl_sync(FULL, bm_h2, i);
            u32 c1 = bm_h1 - ih1 * HB1C - 1u;
            if (!((dupmask >> i) & 1u) && c1 < (u32)VVV &&
                bm_h2 == ih2 * HB2C + c1 + 1u)
                msrc = i * 64 + (int)c1;
        }
        if (dup || lane >= WW) msrc = -1;

        // kill masks: bit i -> extend (beam i, class lane[/+32]) merged or dup
        u32 killLo = dupmask, killHi = dupmask;
        #pragma unroll
        for (int j = 0; j < WW; ++j) {
            int ms = __shfl_sync(FULL, msrc, j);
            if (ms >= 0) {
                int mi = ms >> 6, mc = ms & 63;
                if (mc == lane) killLo |= 1u << mi;
                if (mc == lane + 32) killHi |= 1u << mi;
            }
        }

        // ---- 3: extend keys (scores strictly negative -> ord = ~bits) ----
        u64 key[16];
        #pragma unroll
        for (int i = 0; i < WW; ++i) {
            int   ilast = __shfl_sync(FULL, bm_last, i);
            float ipb   = __shfl_sync(FULL, bm_pb, i);
            float ipt   = __shfl_sync(FULL, bm_ptot, i);
            float sl = ((lane == ilast) ? ipb : ipt) + lp0;
            if ((killLo >> i) & 1u) sl = NEGF;
            u32 lowl = (u32)(((u32)(1015 - 62 * i) << 10) + (u32)i) + Mlow;
            key[i] = ((u64)ord_neg(sl) << 32) | lowl;
            float sh = ((lane + 32 == ilast) ? ipb : ipt) + lp1;
            if ((killHi >> i) & 1u) sh = NEGF;
            u32 lowh = (u32)(((u32)(983 - 62 * i) << 10) + (u32)(i + 8)) + Mlow;
            u64 kh = ((u64)ord_neg(sh) << 32) | lowh;
            key[i + 8] = (lane < 30) ? kh : 0ull;
        }

        // local sort of extends: two sorted 8-lists -> bitonic-split top-8
        SORT8(key, 0);
        SORT8(key, 8);
        u64 T[8];
        #pragma unroll
        for (int k = 0; k < 8; ++k) T[k] = kmax(key[k], key[15 - k]);
        BMERGE8(T);

        // merged stay pnb (MUFU chain; overlaps the sort issue above)
        {
            int mi = (msrc >= 0) ? (msrc >> 6) : 0;
            int mc = (msrc >= 0) ? (msrc & 63) : 0;
            float mpbv = __shfl_sync(FULL, bm_pb, mi);
            float mptv = __shfl_sync(FULL, bm_ptot, mi);
            int   mlv  = __shfl_sync(FULL, bm_last, mi);
            float w0 = __shfl_sync(FULL, lp0, mc & 31);
            float w1 = __shfl_sync(FULL, lp1, mc & 31);
            float lpc = (mc >= 32) ? w1 : w0;
            float bv = ((mc == mlv) ? mpbv : mptv) + lpc;
            bm_mpnb = (msrc >= 0) ? seg_lse2(bm_spnb, bv) : bm_spnb;
        }
        // stay candidate (slot 16, idx = lane): max with tail + 7-CE bubble
        // insert (list is sorted except possibly the last element)
        float cs0 = dup ? NEGF : lax_logaddexp(bm_spb, bm_mpnb);
        u64 key16 = (lane < WW)
            ? (((u64)ord_neg(cs0) << 32) |
               (u32)(((1023u << 10) + 16u) + Mlow))
            : 0ull;
        T[7] = kmax(T[7], key16);
        cex(T[6], T[7]); cex(T[5], T[6]); cex(T[4], T[5]); cex(T[3], T[4]);
        cex(T[2], T[3]); cex(T[1], T[2]); cex(T[0], T[1]);
        // T = local top-8 sorted desc

        // ---- 3.5: OVERLAP — softmax of frame t+1 + prefetch t+2 ----
        float lpn0, lpn1;
        {
            u32 mo = __reduce_max_sync(FULL, ord_of_float(fmaxf(nx0, nx1)));
            float mx = float_of_ord(mo);
            float e0 = expf(nx0 - mx);
            float e1 = (lane < 31) ? expf(nx1 - mx) : 0.0f;
            float sm = e0 + e1;
            #pragma unroll
            for (int off = 16; off; off >>= 1)
                sm += __shfl_xor_sync(FULL, sm, off);
            float lse = logf(sm);
            lpn0 = nx0 - mx - lse;
            lpn1 = nx1 - mx - lse;
        }
        {
            int tn = (t + 2 < TT) ? (t + 2) : (TT - 1);
            const float* nf = base + tn * CCC;
            nx0 = nf[lane];
            nx1 = (lane < 31) ? nf[lane + 32] : NINF;
        }

        // ---- 4: top-8 via REDUX head-pop (branchless) ----
        u32 sel_m = 0u, sel_lo = 0u;   // lane k holds pass-k winner
        #pragma unroll
        for (int k2 = 0; k2 < WW; ++k2) {
            u32 hi = (u32)(T[0] >> 32), lo = (u32)T[0];
            u32 m  = __reduce_max_sync(FULL, hi);
            u32 tx = (hi == m) ? lo : 0u;
            u32 lw = __reduce_max_sync(FULL, tx);
            if (lane == k2) { sel_m = m; sel_lo = lw; }
            bool p = (lane == (int)((lw >> 5) & 31u));  // unique winner lane
            #pragma unroll
            for (int k = 0; k < 7; ++k) T[k] = p ? T[k + 1] : T[k];
            T[7] = p ? 0ull : T[7];
        }

        // ---- 5: commit (gathers via shfl from OLD beam regs) ----
        int idx  = 1023 - (int)(sel_lo >> 10);
        bool stay = idx < WW;
        int slot = (int)(sel_lo & 31u);
        int wl   = (int)((sel_lo >> 5) & 31u);
        int src  = stay ? idx : (slot & 7);
        int c    = wl + ((slot & 8) ? 32 : 0);
        u32 g_h1   = __shfl_sync(FULL, bm_h1, src);
        u32 g_h2   = __shfl_sync(FULL, bm_h2, src);
        int g_last = __shfl_sync(FULL, bm_last, src);
        int g_len  = __shfl_sync(FULL, bm_len, src);
        float g_spb  = __shfl_sync(FULL, bm_spb, src);
        float g_mpnb = __shfl_sync(FULL, bm_mpnb, src);
        if (lane < WW) {
            bool alive = sel_m > ordDeadThr;
            float score = float_of_ord(sel_m);
            float npb  = stay ? g_spb  : NEGF;
            float npnb = stay ? g_mpnb : score;
            if (!alive) { npb = NEGF; npnb = NEGF; }
            bm_pb = npb; bm_pnb = npnb;
            bm_h1 = stay ? g_h1 : (g_h1 * HB1C + (u32)(c + 1));
            bm_h2 = stay ? g_h2 : (g_h2 * HB2C + (u32)(c + 1));
            bm_last = stay ? g_last : c;
            bm_len  = g_len + (stay ? 0 : 1);
            hist[wip][t * WW + lane] = stay
                ? (unsigned short)(idx << 8)
                : (unsigned short)(((slot & 7) << 8) | (c + 1));
        }
        lp0 = lpn0; lp1 = lpn1;
        dupmask = 0u;          // duplicates only possible at t=0
    }

    // ---- outputs: decoded [B*128], lengths [B], prob [B], all f32 ----
    float* dec = out + (size_t)b * TT;
    #pragma unroll
    for (int s2 = 0; s2 < 4; ++s2)
        dec[lane + 32 * s2] = -1.0f;
    __syncwarp();
    int len0 = __shfl_sync(FULL, bm_len, 0);
    float pb0  = __shfl_sync(FULL, bm_pb, 0);
    float pnb0 = __shfl_sync(FULL, bm_pnb, 0);
    if (lane == 0) {
        int cur = 0;
        int pos = len0 - 1;
        for (int tt = TT - 1; tt >= 0; --tt) {
            unsigned short h = hist[wip][tt * WW + cur];
            int cc = (int)(h & 0xFF) - 1;
            cur = h >> 8;
            if (cc >= 0) dec[pos--] = (float)cc;
        }
        out[(size_t)BATCH * TT + b] = (float)len0;
        out[(size_t)BATCH * TT + BATCH + b] = expf(lax_logaddexp(pb0, pnb0));
    }
}

extern "C" void kernel_launch(void* const* d_in, const int* in_sizes, int n_in,
                              void* d_out, int out_size) {
    const float* logits = (const float*)d_in[0];
    float* out = (float*)d_out;
    ctc_beam_kernel<<<BATCH / WPB, 32 * WPB>>>(logits, out);
}

// round 16
// speedup vs baseline: 1.9335x; 1.0624x over previous
#include <cuda_runtime.h>
#include <cstdint>

// CTC prefix beam search — bit-exact vs JAX reference.
// One warp per batch element (1024 warps — TLP is load-bearing).
// R16 = R15 + peeled exact t=0 step (steady loop drops all dup logic),
//       live-region-trimmed pop shifts, alive-check removed (provably true).

#define BATCH 1024
#define TT    128
#define CCC   63
#define VVV   62
#define WW    8
#define NEGF  (-1e30f)
#define HB1C  1000003u
#define HB2C  2654435761u
#define WPB   4
#define FULL  0xffffffffu

typedef unsigned long long u64;
typedef unsigned int u32;

__device__ __forceinline__ float lax_logaddexp(float a, float b) {
    float m = fmaxf(a, b);
    return m + log1pf(expf(-fabsf(a - b)));
}
__device__ __forceinline__ float seg_lse2(float a, float b) {
    float m = fmaxf(a, b);
    float s = expf(a - m) + expf(b - m);
    return logf(fmaxf(s, 1e-30f)) + m;
}
__device__ __forceinline__ u32 ord_of_float(float f) {
    u32 u = __float_as_uint(f);
    return (u & 0x80000000u) ? ~u : (u | 0x80000000u);
}
// encode for STRICTLY NEGATIVE floats (all candidate scores are < 0)
__device__ __forceinline__ u32 ord_neg(float f) {
    return ~__float_as_uint(f);
}
__device__ __forceinline__ float float_of_ord(u32 u) {
    return __uint_as_float((u & 0x80000000u) ? (u & 0x7fffffffu) : ~u);
}
__device__ __forceinline__ u64 kmax(u64 a, u64 b) { return a > b ? a : b; }
__device__ __forceinline__ void cex(u64& a, u64& b) {
    u64 mx = a > b ? a : b;
    u64 mn = a > b ? b : a;
    a = mx; b = mn;
}
// bitonic merge (desc) of a bitonic 8-seq -> sorted desc (validated)
#define BMERGE8(T)                                                   \
    do {                                                             \
        cex(T[0], T[4]); cex(T[1], T[5]); cex(T[2], T[6]); cex(T[3], T[7]); \
        cex(T[0], T[2]); cex(T[1], T[3]); cex(T[4], T[6]); cex(T[5], T[7]); \
        cex(T[0], T[1]); cex(T[2], T[3]); cex(T[4], T[5]); cex(T[6], T[7]); \
    } while (0)
// Batcher 19-CE sort (desc) of 8 (validated)
#define SORT8(K, O)                                                     \
    do {                                                                \
        cex(K[O+0],K[O+1]); cex(K[O+2],K[O+3]); cex(K[O+4],K[O+5]); cex(K[O+6],K[O+7]); \
        cex(K[O+0],K[O+2]); cex(K[O+1],K[O+3]); cex(K[O+4],K[O+6]); cex(K[O+5],K[O+7]); \
        cex(K[O+1],K[O+2]); cex(K[O+5],K[O+6]);                          \
        cex(K[O+0],K[O+4]); cex(K[O+1],K[O+5]); cex(K[O+2],K[O+6]); cex(K[O+3],K[O+7]); \
        cex(K[O+2],K[O+4]); cex(K[O+3],K[O+5]);                          \
        cex(K[O+1],K[O+2]); cex(K[O+3],K[O+4]); cex(K[O+5],K[O+6]);      \
    } while (0)

__global__ void ctc_beam_kernel(const float* __restrict__ logits,
                                float* __restrict__ out) {
    __shared__ unsigned short hist[WPB][TT * WW];  // (parent<<8)|(char+1)
    const int wip  = threadIdx.x >> 5;
    const int lane = threadIdx.x & 31;
    const int b    = blockIdx.x * WPB + wip;
    const float* base = logits + (size_t)b * TT * CCC;
    const float NINF = __int_as_float(0xff800000);
    const u32 Mlow = ((u32)lane << 5) - ((u32)lane << 10);

    // beam state (valid on lanes 0..7; lane j == beam j)
    u32 bm_h1 = 1u, bm_h2 = 1u;
    float bm_pb  = (lane == 0) ? 0.0f : NEGF;
    float bm_pnb = NEGF;
    int bm_last = -1, bm_len = 0;
    float bm_spb = NEGF, bm_mpnb = NEGF;

    // softmax frame 0
    float lp0, lp1;
    {
        float cx0 = base[lane];
        float cx1 = (lane < 31) ? base[lane + 32] : NINF;
        u32 mo = __reduce_max_sync(FULL, ord_of_float(fmaxf(cx0, cx1)));
        float mx = float_of_ord(mo);
        float e0 = expf(cx0 - mx);
        float e1 = (lane < 31) ? expf(cx1 - mx) : 0.0f;
        float sm = e0 + e1;
        #pragma unroll
        for (int off = 16; off; off >>= 1)
            sm += __shfl_xor_sync(FULL, sm, off);
        float lse = logf(sm);
        lp0 = cx0 - mx - lse;
        lp1 = cx1 - mx - lse;
    }
    // prefetch frame 1
    float nx0 = base[CCC + lane];
    float nx1 = (lane < 31) ? base[CCC + lane + 32] : NINF;

    // ================= t = 0 : specialized exact step =================
    // Only beam 0 alive (ptot = 0 exactly); beams 1..7 are duplicates whose
    // candidates the reference kills. No merges possible. Candidate set:
    // extend(beam0, c) with score lp[c] (FADD 0+x exact), idx 8+c;
    // stay(beam0) score lp[62] (logaddexp with NEG is exact), idx 0.
    {
        float lpBlank = __shfl_sync(FULL, lp1, 30);   // lp[62]
        u64 T[8];
        {
            u64 kLo = ((u64)ord_neg(lp0) << 32) |
                      ((u32)((u32)1015 << 10) + Mlow);           // i=0, slot 0
            u64 kHi = ((u64)ord_neg(lp1) << 32) |
                      ((u32)(((u32)983 << 10) + 8u) + Mlow);     // i=0, slot 8
            if (lane >= 30) kHi = 0ull;
            u64 kSt = (lane == 0)
                ? (((u64)ord_neg(lpBlank) << 32) | (u32)((1023u << 10) + 16u))
                : 0ull;
            T[0] = kLo; T[1] = kHi; T[2] = kSt;
            cex(T[0], T[1]); cex(T[1], T[2]); cex(T[0], T[1]);
            T[3] = T[4] = T[5] = T[6] = T[7] = 0ull;
        }
        bm_spb  = lpBlank;   // beam0 stay pb; only lane 0's value is consulted
        bm_mpnb = NEGF;

        // overlap: softmax of frame 1 + prefetch frame 2
        float lpn0, lpn1;
        {
            u32 mo = __reduce_max_sync(FULL, ord_of_float(fmaxf(nx0, nx1)));
            float mx = float_of_ord(mo);
            float e0 = expf(nx0 - mx);
            float e1 = (lane < 31) ? expf(nx1 - mx) : 0.0f;
            float sm = e0 + e1;
            #pragma unroll
            for (int off = 16; off; off >>= 1)
                sm += __shfl_xor_sync(FULL, sm, off);
            float lse = logf(sm);
            lpn0 = nx0 - mx - lse;
            lpn1 = nx1 - mx - lse;
        }
        {
            const float* nf = base + 2 * CCC;
            nx0 = nf[lane];
            nx1 = (lane < 31) ? nf[lane + 32] : NINF;
        }

        // top-8 via REDUX head-pop (trimmed shifts)
        u32 sel_m = 0u, sel_lo = 0u;
        #pragma unroll
        for (int k2 = 0; k2 < WW; ++k2) {
            u32 hi = (u32)(T[0] >> 32), lo = (u32)T[0];
            u32 m  = __reduce_max_sync(FULL, hi);
            u32 tx = (hi == m) ? lo : 0u;
            u32 lw = __reduce_max_sync(FULL, tx);
            if (lane == k2) { sel_m = m; sel_lo = lw; }
            bool p = (lane == (int)((lw >> 5) & 31u));
            #pragma unroll
            for (int k = 0; k < 7 - k2; ++k) T[k] = p ? T[k + 1] : T[k];
        }

        // commit (identical to general commit; src is always beam 0 here)
        int idx  = 1023 - (int)(sel_lo >> 10);
        bool stay = idx < WW;
        int slot = (int)(sel_lo & 31u);
        int wl   = (int)((sel_lo >> 5) & 31u);
        int src  = stay ? idx : (slot & 7);
        int c    = wl + ((slot & 8) ? 32 : 0);
        u32 g_h1   = __shfl_sync(FULL, bm_h1, src);
        u32 g_h2   = __shfl_sync(FULL, bm_h2, src);
        int g_last = __shfl_sync(FULL, bm_last, src);
        int g_len  = __shfl_sync(FULL, bm_len, src);
        float g_spb  = __shfl_sync(FULL, bm_spb, src);
        float g_mpnb = __shfl_sync(FULL, bm_mpnb, src);
        if (lane < WW) {
            float score = float_of_ord(sel_m);
            bm_pb  = stay ? g_spb  : NEGF;
            bm_pnb = stay ? g_mpnb : score;
            bm_h1 = stay ? g_h1 : (g_h1 * HB1C + (u32)(c + 1));
            bm_h2 = stay ? g_h2 : (g_h2 * HB2C + (u32)(c + 1));
            bm_last = stay ? g_last : c;
            bm_len  = g_len + (stay ? 0 : 1);
            hist[wip][lane] = stay
                ? (unsigned short)(idx << 8)
                : (unsigned short)(((slot & 7) << 8) | (c + 1));
        }
        lp0 = lpn0; lp1 = lpn1;
    }

    // ================= steady loop: t = 1 .. 127 (no dup logic) =========
    for (int t = 1; t < TT; ++t) {
        // ---- 2a: per-beam prep ----
        float lpBlank = __shfl_sync(FULL, lp1, 30);   // class 62
        int ls = (bm_last >= 0) ? (bm_last & 31) : 0;
        float v0 = __shfl_sync(FULL, lp0, ls);
        float v1 = __shfl_sync(FULL, lp1, ls);
        float lpLast = (bm_last >= 32) ? v1 : v0;

        float bm_ptot = lax_logaddexp(bm_pb, bm_pnb);
        bm_spb = bm_ptot + lpBlank;
        float bm_spnb = (bm_last >= 0) ? (bm_pnb + lpLast) : NEGF;

        // ---- 2b: inverted merge detection ----
        int msrc = -1;
        #pragma unroll
        for (int i = 0; i < WW; ++i) {
            u32 ih1 = __shfl_sync(FULL, bm_h1, i);
            u32 ih2 = __shfl_sync(FULL, bm_h2, i);
            u32 c1 = bm_h1 - ih1 * HB1C - 1u;
            if (c1 < (u32)VVV && bm_h2 == ih2 * HB2C + c1 + 1u)
                msrc = i * 64 + (int)c1;
        }
        if (lane >= WW) msrc = -1;

        // kill masks: bit i -> extend (beam i, class lane[/+32]) merged away
        u32 killLo = 0u, killHi = 0u;
        #pragma unroll
        for (int j = 0; j < WW; ++j) {
            int ms = __shfl_sync(FULL, msrc, j);
            if (ms >= 0) {
                int mi = ms >> 6, mc = ms & 63;
                if (mc == lane) killLo |= 1u << mi;
                if (mc == lane + 32) killHi |= 1u << mi;
            }
        }

        // ---- 3: extend keys (scores strictly negative -> ord = ~bits) ----
        u64 key[16];
        #pragma unroll
        for (int i = 0; i < WW; ++i) {
            int   ilast = __shfl_sync(FULL, bm_last, i);
            float ipb   = __shfl_sync(FULL, bm_pb, i);
            float ipt   = __shfl_sync(FULL, bm_ptot, i);
            float sl = ((lane == ilast) ? ipb : ipt) + lp0;
            if ((killLo >> i) & 1u) sl = NEGF;
            u32 lowl = (u32)(((u32)(1015 - 62 * i) << 10) + (u32)i) + Mlow;
            key[i] = ((u64)ord_neg(sl) << 32) | lowl;
            float sh = ((lane + 32 == ilast) ? ipb : ipt) + lp1;
            if ((killHi >> i) & 1u) sh = NEGF;
            u32 lowh = (u32)(((u32)(983 - 62 * i) << 10) + (u32)(i + 8)) + Mlow;
            u64 kh = ((u64)ord_neg(sh) << 32) | lowh;
            key[i + 8] = (lane < 30) ? kh : 0ull;
        }

        // local sort of extends: two sorted 8-lists -> bitonic-split top-8
        SORT8(key, 0);
        SORT8(key, 8);
        u64 T[8];
        #pragma unroll
        for (int k = 0; k < 8; ++k) T[k] = kmax(key[k], key[15 - k]);
        BMERGE8(T);

        // merged stay pnb (MUFU chain; overlaps the sort issue above)
        {
            int mi = (msrc >= 0) ? (msrc >> 6) : 0;
            int mc = (msrc >= 0) ? (msrc & 63) : 0;
            float mpbv = __shfl_sync(FULL, bm_pb, mi);
            float mptv = __shfl_sync(FULL, bm_ptot, mi);
            int   mlv  = __shfl_sync(FULL, bm_last, mi);
            float w0 = __shfl_sync(FULL, lp0, mc & 31);
            float w1 = __shfl_sync(FULL, lp1, mc & 31);
            float lpc = (mc >= 32) ? w1 : w0;
            float bv = ((mc == mlv) ? mpbv : mptv) + lpc;
            bm_mpnb = (msrc >= 0) ? seg_lse2(bm_spnb, bv) : bm_spnb;
        }
        // stay candidate (slot 16, idx = lane): max with tail + 7-CE bubble
        float cs0 = lax_logaddexp(bm_spb, bm_mpnb);
        u64 key16 = (lane < WW)
            ? (((u64)ord_neg(cs0) << 32) |
               (u32)(((1023u << 10) + 16u) + Mlow))
            : 0ull;
        T[7] = kmax(T[7], key16);
        cex(T[6], T[7]); cex(T[5], T[6]); cex(T[4], T[5]); cex(T[3], T[4]);
        cex(T[2], T[3]); cex(T[1], T[2]); cex(T[0], T[1]);

        // ---- 3.5: OVERLAP — softmax of frame t+1 + prefetch t+2 ----
        float lpn0, lpn1;
        {
            u32 mo = __reduce_max_sync(FULL, ord_of_float(fmaxf(nx0, nx1)));
            float mx = float_of_ord(mo);
            float e0 = expf(nx0 - mx);
            float e1 = (lane < 31) ? expf(nx1 - mx) : 0.0f;
            float sm = e0 + e1;
            #pragma unroll
            for (int off = 16; off; off >>= 1)
                sm += __shfl_xor_sync(FULL, sm, off);
            float lse = logf(sm);
            lpn0 = nx0 - mx - lse;
            lpn1 = nx1 - mx - lse;
        }
        {
            int tn = (t + 2 < TT) ? (t + 2) : (TT - 1);
            const float* nf = base + tn * CCC;
            nx0 = nf[lane];
            nx1 = (lane < 31) ? nf[lane + 32] : NINF;
        }

        // ---- 4: top-8 via REDUX head-pop (trimmed shifts) ----
        u32 sel_m = 0u, sel_lo = 0u;   // lane k holds pass-k winner
        #pragma unroll
        for (int k2 = 0; k2 < WW; ++k2) {
            u32 hi = (u32)(T[0] >> 32), lo = (u32)T[0];
            u32 m  = __reduce_max_sync(FULL, hi);
            u32 tx = (hi == m) ? lo : 0u;
            u32 lw = __reduce_max_sync(FULL, tx);
            if (lane == k2) { sel_m = m; sel_lo = lw; }
            bool p = (lane == (int)((lw >> 5) & 31u));  // unique winner lane
            #pragma unroll
            for (int k = 0; k < 7 - k2; ++k) T[k] = p ? T[k + 1] : T[k];
        }

        // ---- 5: commit (gathers via shfl from OLD beam regs) ----
        int idx  = 1023 - (int)(sel_lo >> 10);
        bool stay = idx < WW;
        int slot = (int)(sel_lo & 31u);
        int wl   = (int)((sel_lo >> 5) & 31u);
        int src  = stay ? idx : (slot & 7);
        int c    = wl + ((slot & 8) ? 32 : 0);
        u32 g_h1   = __shfl_sync(FULL, bm_h1, src);
        u32 g_h2   = __shfl_sync(FULL, bm_h2, src);
        int g_last = __shfl_sync(FULL, bm_last, src);
        int g_len  = __shfl_sync(FULL, bm_len, src);
        float g_spb  = __shfl_sync(FULL, bm_spb, src);
        float g_mpnb = __shfl_sync(FULL, bm_mpnb, src);
        if (lane < WW) {
            float score = float_of_ord(sel_m);
            bm_pb  = stay ? g_spb  : NEGF;
            bm_pnb = stay ? g_mpnb : score;
            bm_h1 = stay ? g_h1 : (g_h1 * HB1C + (u32)(c + 1));
            bm_h2 = stay ? g_h2 : (g_h2 * HB2C + (u32)(c + 1));
            bm_last = stay ? g_last : c;
            bm_len  = g_len + (stay ? 0 : 1);
            hist[wip][t * WW + lane] = stay
                ? (unsigned short)(idx << 8)
                : (unsigned short)(((slot & 7) << 8) | (c + 1));
        }
        lp0 = lpn0; lp1 = lpn1;
    }

    // ---- outputs: decoded [B*128], lengths [B], prob [B], all f32 ----
    float* dec = out + (size_t)b * TT;
    #pragma unroll
    for (int s2 = 0; s2 < 4; ++s2)
        dec[lane + 32 * s2] = -1.0f;
    __syncwarp();
    int len0 = __shfl_sync(FULL, bm_len, 0);
    float pb0  = __shfl_sync(FULL, bm_pb, 0);
    float pnb0 = __shfl_sync(FULL, bm_pnb, 0);
    if (lane == 0) {
        int cur = 0;
        int pos = len0 - 1;
        for (int tt = TT - 1; tt >= 0; --tt) {
            unsigned short h = hist[wip][tt * WW + cur];
            int cc = (int)(h & 0xFF) - 1;
            cur = h >> 8;
            if (cc >= 0) dec[pos--] = (float)cc;
        }
        out[(size_t)BATCH * TT + b] = (float)len0;
        out[(size_t)BATCH * TT + BATCH + b] = expf(lax_logaddexp(pb0, pnb0));
    }
}

extern "C" void kernel_launch(void* const* d_in, const int* in_sizes, int n_in,
                              void* d_out, int out_size) {
    const float* logits = (const float*)d_in[0];
    float* out = (float*)d_out;
    ctc_beam_kernel<<<BATCH / WPB, 32 * WPB>>>(logits, out);
}

// round 17
// speedup vs baseline: 2.0857x; 1.0787x over previous
#include <cuda_runtime.h>
#include <cstdint>

// CTC prefix beam search — bit-exact vs JAX reference.
// One warp per batch element (1024 warps — TLP is load-bearing).
// R17 = R16 + min-order raw-bit keys (no ord NOTs; scores provably negative),
//       merge-free step skip (warp-uniform ballot), pre-multiplied hash shfl.

#define BATCH 1024
#define TT    128
#define CCC   63
#define VVV   62
#define WW    8
#define NEGF  (-1e30f)
#define HB1C  1000003u
#define HB2C  2654435761u
#define WPB   4
#define FULL  0xffffffffu

typedef unsigned long long u64;
typedef unsigned int u32;

__device__ __forceinline__ float lax_logaddexp(float a, float b) {
    float m = fmaxf(a, b);
    return m + log1pf(expf(-fabsf(a - b)));
}
__device__ __forceinline__ float seg_lse2(float a, float b) {
    float m = fmaxf(a, b);
    float s = expf(a - m) + expf(b - m);
    return logf(fmaxf(s, 1e-30f)) + m;
}
__device__ __forceinline__ u32 ord_of_float(float f) {   // softmax max only
    u32 u = __float_as_uint(f);
    return (u & 0x80000000u) ? ~u : (u | 0x80000000u);
}
__device__ __forceinline__ float float_of_ord(u32 u) {
    return __uint_as_float((u & 0x80000000u) ? (u & 0x7fffffffu) : ~u);
}
// MIN-order keys: raw bits of a NEGATIVE float ascend as score descends.
__device__ __forceinline__ u64 kmin(u64 a, u64 b) { return a < b ? a : b; }
__device__ __forceinline__ void cex(u64& a, u64& b) {    // a keeps MIN
    u64 mn = a < b ? a : b;
    u64 mx = a < b ? b : a;
    a = mn; b = mx;
}
// bitonic merge (asc) of a bitonic 8-seq -> sorted asc
#define BMERGE8(T)                                                   \
    do {                                                             \
        cex(T[0], T[4]); cex(T[1], T[5]); cex(T[2], T[6]); cex(T[3], T[7]); \
        cex(T[0], T[2]); cex(T[1], T[3]); cex(T[4], T[6]); cex(T[5], T[7]); \
        cex(T[0], T[1]); cex(T[2], T[3]); cex(T[4], T[5]); cex(T[6], T[7]); \
    } while (0)
// Batcher 19-CE sort (asc) of 8
#define SORT8(K, O)                                                     \
    do {                                                                \
        cex(K[O+0],K[O+1]); cex(K[O+2],K[O+3]); cex(K[O+4],K[O+5]); cex(K[O+6],K[O+7]); \
        cex(K[O+0],K[O+2]); cex(K[O+1],K[O+3]); cex(K[O+4],K[O+6]); cex(K[O+5],K[O+7]); \
        cex(K[O+1],K[O+2]); cex(K[O+5],K[O+6]);                          \
        cex(K[O+0],K[O+4]); cex(K[O+1],K[O+5]); cex(K[O+2],K[O+6]); cex(K[O+3],K[O+7]); \
        cex(K[O+2],K[O+4]); cex(K[O+3],K[O+5]);                          \
        cex(K[O+1],K[O+2]); cex(K[O+3],K[O+4]); cex(K[O+5],K[O+6]);      \
    } while (0)

__global__ void ctc_beam_kernel(const float* __restrict__ logits,
                                float* __restrict__ out) {
    __shared__ unsigned short hist[WPB][TT * WW];  // (parent<<8)|(char+1)
    const int wip  = threadIdx.x >> 5;
    const int lane = threadIdx.x & 31;
    const int b    = blockIdx.x * WPB + wip;
    const float* base = logits + (size_t)b * TT * CCC;
    const float NINF = __int_as_float(0xff800000);
    // payload = (idx<<10)|(lane<<5)|slot; lower payload == lower idx (tie rule)
    const u32 PB = ((u32)lane << 10) + ((u32)lane << 5);

    // beam state (valid on lanes 0..7; lane j == beam j)
    u32 bm_h1 = 1u, bm_h2 = 1u;
    float bm_pb  = (lane == 0) ? 0.0f : NEGF;
    float bm_pnb = NEGF;
    int bm_last = -1, bm_len = 0;
    float bm_spb = NEGF, bm_mpnb = NEGF;

    // softmax frame 0
    float lp0, lp1;
    {
        float cx0 = base[lane];
        float cx1 = (lane < 31) ? base[lane + 32] : NINF;
        u32 mo = __reduce_max_sync(FULL, ord_of_float(fmaxf(cx0, cx1)));
        float mx = float_of_ord(mo);
        float e0 = expf(cx0 - mx);
        float e1 = (lane < 31) ? expf(cx1 - mx) : 0.0f;
        float sm = e0 + e1;
        #pragma unroll
        for (int off = 16; off; off >>= 1)
            sm += __shfl_xor_sync(FULL, sm, off);
        float lse = logf(sm);
        lp0 = cx0 - mx - lse;
        lp1 = cx1 - mx - lse;
    }
    // prefetch frame 1
    float nx0 = base[CCC + lane];
    float nx1 = (lane < 31) ? base[CCC + lane + 32] : NINF;

    // ================= t = 0 : specialized exact step =================
    {
        float lpBlank = __shfl_sync(FULL, lp1, 30);   // lp[62]
        u64 T[8];
        {
            // idx(kLo)=8+lane, idx(kHi)=40+lane, idx(stay lane0)=0
            u64 kLo = ((u64)__float_as_uint(lp0) << 32) |
                      (u32)((8u << 10) + PB);                 // slot 0
            u64 kHi = ((u64)__float_as_uint(lp1) << 32) |
                      (u32)(((40u << 10) + 8u) + PB);         // slot 8
            if (lane >= 30) kHi = ~0ull;
            u64 kSt = (lane == 0)
                ? (((u64)__float_as_uint(lpBlank) << 32) | 16u)
                : ~0ull;
            T[0] = kLo; T[1] = kHi; T[2] = kSt;
            cex(T[0], T[1]); cex(T[1], T[2]); cex(T[0], T[1]);
            T[3] = T[4] = T[5] = T[6] = T[7] = ~0ull;
        }
        bm_spb  = lpBlank;   // beam0 stay pb; only lane 0's value is consulted
        bm_mpnb = NEGF;

        // overlap: softmax of frame 1 + prefetch frame 2
        float lpn0, lpn1;
        {
            u32 mo = __reduce_max_sync(FULL, ord_of_float(fmaxf(nx0, nx1)));
            float mx = float_of_ord(mo);
            float e0 = expf(nx0 - mx);
            float e1 = (lane < 31) ? expf(nx1 - mx) : 0.0f;
            float sm = e0 + e1;
            #pragma unroll
            for (int off = 16; off; off >>= 1)
                sm += __shfl_xor_sync(FULL, sm, off);
            float lse = logf(sm);
            lpn0 = nx0 - mx - lse;
            lpn1 = nx1 - mx - lse;
        }
        {
            const float* nf = base + 2 * CCC;
            nx0 = nf[lane];
            nx1 = (lane < 31) ? nf[lane + 32] : NINF;
        }

        // top-8 via min-REDUX head-pop (trimmed shifts)
        u32 sel_m = 0u, sel_lo = 0u;
        #pragma unroll
        for (int k2 = 0; k2 < WW; ++k2) {
            u32 hi = (u32)(T[0] >> 32), lo = (u32)T[0];
            u32 m  = __reduce_min_sync(FULL, hi);
            u32 tx = (hi == m) ? lo : 0xffffffffu;
            u32 lw = __reduce_min_sync(FULL, tx);
            if (lane == k2) { sel_m = m; sel_lo = lw; }
            bool p = (lane == (int)((lw >> 5) & 31u));
            #pragma unroll
            for (int k = 0; k < 7 - k2; ++k) T[k] = p ? T[k + 1] : T[k];
        }

        // commit
        int idx  = (int)(sel_lo >> 10);
        bool stay = idx < WW;
        int slot = (int)(sel_lo & 31u);
        int wl   = (int)((sel_lo >> 5) & 31u);
        int src  = stay ? idx : (slot & 7);
        int c    = wl + ((slot & 8) ? 32 : 0);
        u32 g_h1   = __shfl_sync(FULL, bm_h1, src);
        u32 g_h2   = __shfl_sync(FULL, bm_h2, src);
        int g_last = __shfl_sync(FULL, bm_last, src);
        int g_len  = __shfl_sync(FULL, bm_len, src);
        float g_spb  = __shfl_sync(FULL, bm_spb, src);
        float g_mpnb = __shfl_sync(FULL, bm_mpnb, src);
        if (lane < WW) {
            float score = __uint_as_float(sel_m);
            bm_pb  = stay ? g_spb  : NEGF;
            bm_pnb = stay ? g_mpnb : score;
            bm_h1 = stay ? g_h1 : (g_h1 * HB1C + (u32)(c + 1));
            bm_h2 = stay ? g_h2 : (g_h2 * HB2C + (u32)(c + 1));
            bm_last = stay ? g_last : c;
            bm_len  = g_len + (stay ? 0 : 1);
            hist[wip][lane] = stay
                ? (unsigned short)(idx << 8)
                : (unsigned short)(((slot & 7) << 8) | (c + 1));
        }
        lp0 = lpn0; lp1 = lpn1;
    }

    // ================= steady loop: t = 1 .. 127 =================
    for (int t = 1; t < TT; ++t) {
        // ---- 2a: per-beam prep ----
        float lpBlank = __shfl_sync(FULL, lp1, 30);   // class 62
        int ls = (bm_last >= 0) ? (bm_last & 31) : 0;
        float v0 = __shfl_sync(FULL, lp0, ls);
        float v1 = __shfl_sync(FULL, lp1, ls);
        float lpLast = (bm_last >= 32) ? v1 : v0;

        float bm_ptot = lax_logaddexp(bm_pb, bm_pnb);
        bm_spb = bm_ptot + lpBlank;
        float bm_spnb = (bm_last >= 0) ? (bm_pnb + lpLast) : NEGF;

        // ---- 2b: inverted merge detection (pre-multiplied hash shfl) ----
        u32 ph1 = bm_h1 * HB1C;
        u32 ph2 = bm_h2 * HB2C;
        int msrc = -1;
        #pragma unroll
        for (int i = 0; i < WW; ++i) {
            u32 iph1 = __shfl_sync(FULL, ph1, i);
            u32 iph2 = __shfl_sync(FULL, ph2, i);
            u32 c1 = bm_h1 - iph1 - 1u;
            if (c1 < (u32)VVV && bm_h2 == iph2 + c1 + 1u)
                msrc = i * 64 + (int)c1;
        }
        if (lane >= WW) msrc = -1;

        // merge-free steps (warp-uniform) skip kill masks + mpnb gather
        u32 killLo = 0u, killHi = 0u;
        u32 anyMerge = __ballot_sync(FULL, msrc >= 0);
        if (anyMerge) {
            #pragma unroll
            for (int j = 0; j < WW; ++j) {
                int ms = __shfl_sync(FULL, msrc, j);
                if (ms >= 0) {
                    int mi = ms >> 6, mc = ms & 63;
                    if (mc == lane) killLo |= 1u << mi;
                    if (mc == lane + 32) killHi |= 1u << mi;
                }
            }
        }

        // ---- 3: extend keys (min-order raw bits; no ord NOT) ----
        u64 key[16];
        #pragma unroll
        for (int i = 0; i < WW; ++i) {
            int   ilast = __shfl_sync(FULL, bm_last, i);
            float ipb   = __shfl_sync(FULL, bm_pb, i);
            float ipt   = __shfl_sync(FULL, bm_ptot, i);
            float sl = ((lane == ilast) ? ipb : ipt) + lp0;
            if ((killLo >> i) & 1u) sl = NEGF;
            // idx = 8 + 62*i + lane ; slot = i
            u32 lowl = (u32)((((u32)(8 + 62 * i)) << 10) + (u32)i) + PB;
            key[i] = ((u64)__float_as_uint(sl) << 32) | lowl;
            float sh = ((lane + 32 == ilast) ? ipb : ipt) + lp1;
            if ((killHi >> i) & 1u) sh = NEGF;
            // idx = 8 + 62*i + lane + 32 ; slot = i + 8
            u32 lowh = (u32)((((u32)(40 + 62 * i)) << 10) + (u32)(i + 8)) + PB;
            u64 kh = ((u64)__float_as_uint(sh) << 32) | lowh;
            key[i + 8] = (lane < 30) ? kh : ~0ull;
        }

        // local sort of extends: two sorted(asc) 8-lists -> bottom-8 split
        SORT8(key, 0);
        SORT8(key, 8);
        u64 T[8];
        #pragma unroll
        for (int k = 0; k < 8; ++k) T[k] = kmin(key[k], key[15 - k]);
        BMERGE8(T);

        // merged stay pnb (only when a merge exists this step)
        if (anyMerge) {
            int mi = (msrc >= 0) ? (msrc >> 6) : 0;
            int mc = (msrc >= 0) ? (msrc & 63) : 0;
            float mpbv = __shfl_sync(FULL, bm_pb, mi);
            float mptv = __shfl_sync(FULL, bm_ptot, mi);
            int   mlv  = __shfl_sync(FULL, bm_last, mi);
            float w0 = __shfl_sync(FULL, lp0, mc & 31);
            float w1 = __shfl_sync(FULL, lp1, mc & 31);
            float lpc = (mc >= 32) ? w1 : w0;
            float bv = ((mc == mlv) ? mpbv : mptv) + lpc;
            bm_mpnb = (msrc >= 0) ? seg_lse2(bm_spnb, bv) : bm_spnb;
        } else {
            bm_mpnb = bm_spnb;
        }
        // stay candidate (slot 16, idx = lane): min with tail + 7-CE bubble
        float cs0 = lax_logaddexp(bm_spb, bm_mpnb);
        u64 key16 = (lane < WW)
            ? (((u64)__float_as_uint(cs0) << 32) | (u32)(PB + 16u))
            : ~0ull;
        T[7] = kmin(T[7], key16);
        cex(T[6], T[7]); cex(T[5], T[6]); cex(T[4], T[5]); cex(T[3], T[4]);
        cex(T[2], T[3]); cex(T[1], T[2]); cex(T[0], T[1]);

        // ---- 3.5: OVERLAP — softmax of frame t+1 + prefetch t+2 ----
        float lpn0, lpn1;
        {
            u32 mo = __reduce_max_sync(FULL, ord_of_float(fmaxf(nx0, nx1)));
            float mx = float_of_ord(mo);
            float e0 = expf(nx0 - mx);
            float e1 = (lane < 31) ? expf(nx1 - mx) : 0.0f;
            float sm = e0 + e1;
            #pragma unroll
            for (int off = 16; off; off >>= 1)
                sm += __shfl_xor_sync(FULL, sm, off);
            float lse = logf(sm);
            lpn0 = nx0 - mx - lse;
            lpn1 = nx1 - mx - lse;
        }
        {
            int tn = (t + 2 < TT) ? (t + 2) : (TT - 1);
            const float* nf = base + tn * CCC;
            nx0 = nf[lane];
            nx1 = (lane < 31) ? nf[lane + 32] : NINF;
        }

        // ---- 4: top-8 via min-REDUX head-pop (trimmed shifts) ----
        u32 sel_m = 0u, sel_lo = 0u;   // lane k holds pass-k winner
        #pragma unroll
        for (int k2 = 0; k2 < WW; ++k2) {
            u32 hi = (u32)(T[0] >> 32), lo = (u32)T[0];
            u32 m  = __reduce_min_sync(FULL, hi);
            u32 tx = (hi == m) ? lo : 0xffffffffu;
            u32 lw = __reduce_min_sync(FULL, tx);
            if (lane == k2) { sel_m = m; sel_lo = lw; }
            bool p = (lane == (int)((lw >> 5) & 31u));  // unique winner lane
            #pragma unroll
            for (int k = 0; k < 7 - k2; ++k) T[k] = p ? T[k + 1] : T[k];
        }

        // ---- 5: commit (gathers via shfl from OLD beam regs) ----
        int idx  = (int)(sel_lo >> 10);
        bool stay = idx < WW;
        int slot = (int)(sel_lo & 31u);
        int wl   = (int)((sel_lo >> 5) & 31u);
        int src  = stay ? idx : (slot & 7);
        int c    = wl + ((slot & 8) ? 32 : 0);
        u32 g_h1   = __shfl_sync(FULL, bm_h1, src);
        u32 g_h2   = __shfl_sync(FULL, bm_h2, src);
        int g_last = __shfl_sync(FULL, bm_last, src);
        int g_len  = __shfl_sync(FULL, bm_len, src);
        float g_spb  = __shfl_sync(FULL, bm_spb, src);
        float g_mpnb = __shfl_sync(FULL, bm_mpnb, src);
        if (lane < WW) {
            float score = __uint_as_float(sel_m);
            bm_pb  = stay ? g_spb  : NEGF;
            bm_pnb = stay ? g_mpnb : score;
            bm_h1 = stay ? g_h1 : (g_h1 * HB1C + (u32)(c + 1));
            bm_h2 = stay ? g_h2 : (g_h2 * HB2C + (u32)(c + 1));
            bm_last = stay ? g_last : c;
            bm_len  = g_len + (stay ? 0 : 1);
            hist[wip][t * WW + lane] = stay
                ? (unsigned short)(idx << 8)
                : (unsigned short)(((slot & 7) << 8) | (c + 1));
        }
        lp0 = lpn0; lp1 = lpn1;
    }

    // ---- outputs: decoded [B*128], lengths [B], prob [B], all f32 ----
    float* dec = out + (size_t)b * TT;
    #pragma unroll
    for (int s2 = 0; s2 < 4; ++s2)
        dec[lane + 32 * s2] = -1.0f;
    __syncwarp();
    int len0 = __shfl_sync(FULL, bm_len, 0);
    float pb0  = __shfl_sync(FULL, bm_pb, 0);
    float pnb0 = __shfl_sync(FULL, bm_pnb, 0);
    if (lane == 0) {
        int cur = 0;
        int pos = len0 - 1;
        for (int tt = TT - 1; tt >= 0; --tt) {
            unsigned short h = hist[wip][tt * WW + cur];
            int cc = (int)(h & 0xFF) - 1;
            cur = h >> 8;
            if (cc >= 0) dec[pos--] = (float)cc;
        }
        out[(size_t)BATCH * TT + b] = (float)len0;
        out[(size_t)BATCH * TT + BATCH + b] = expf(lax_logaddexp(pb0, pnb0));
    }
}

extern "C" void kernel_launch(void* const* d_in, const int* in_sizes, int n_in,
                              void* d_out, int out_size) {
    const float* logits = (const float*)d_in[0];
    float* out = (float*)d_out;
    ctc_beam_kernel<<<BATCH / WPB, 32 * WPB>>>(logits, out);
}